// round 3
// baseline (speedup 1.0000x reference)
#include <cuda_runtime.h>

// Fixed problem shapes
#define N_   100000
#define R_   4
#define E_   500000
#define IN_  256
#define HID_ 128
#define OUT_ 64

// Scratch (no allocation allowed -> device globals)
__device__ float g_h[(size_t)N_ * HID_];     // per-relation transformed features (reused layer 2, N*64 <= N*128)
__device__ float g_out1[(size_t)N_ * HID_];  // layer-1 accumulated output (pre-ReLU)
__device__ float g_degO[R_ * N_];            // per-relation rsqrt(max(deg_out,1))
__device__ float g_degI[R_ * N_];            // per-relation rsqrt(max(deg_in,1))

// ---------------------------------------------------------------------------
// Degree kernels
// ---------------------------------------------------------------------------
__global__ void zero_deg_kernel() {
    int i = blockIdx.x * blockDim.x + threadIdx.x;
    if (i < R_ * N_) {
        g_degO[i] = 0.0f;
        g_degI[i] = 0.0f;
    }
}

__global__ void count_deg_kernel(const int* __restrict__ src, const int* __restrict__ dst) {
    int i = blockIdx.x * blockDim.x + threadIdx.x;
    if (i < R_ * E_) {
        int r = i / E_;
        atomicAdd(&g_degO[r * N_ + src[i]], 1.0f);
        atomicAdd(&g_degI[r * N_ + dst[i]], 1.0f);
    }
}

__global__ void finalize_deg_kernel() {
    int i = blockIdx.x * blockDim.x + threadIdx.x;
    if (i < R_ * N_) {
        g_degO[i] = rsqrtf(fmaxf(g_degO[i], 1.0f));
        g_degI[i] = rsqrtf(fmaxf(g_degI[i], 1.0f));
    }
}

// ---------------------------------------------------------------------------
// Output init: out[n][k] = sum_r b[r][k]
// ---------------------------------------------------------------------------
__global__ void init_out1_kernel(const float* __restrict__ b1) {
    int i = blockIdx.x * blockDim.x + threadIdx.x;
    if (i < N_ * HID_) {
        int k = i & (HID_ - 1);
        float s = 0.0f;
#pragma unroll
        for (int r = 0; r < R_; r++) s += b1[r * HID_ + k];
        g_out1[i] = s;
    }
}

__global__ void init_out2_kernel(const float* __restrict__ b2, float* __restrict__ out) {
    int i = blockIdx.x * blockDim.x + threadIdx.x;
    if (i < N_ * OUT_) {
        int k = i & (OUT_ - 1);
        float s = 0.0f;
#pragma unroll
        for (int r = 0; r < R_; r++) s += b2[r * OUT_ + k];
        out[i] = s;
    }
}

// ---------------------------------------------------------------------------
// Row-scaled GEMM:  C = diag(rsqrt_deg_out[r]) * (relu?(A)) * W[r]
//   A: [N_, K] row-major (LAYER==1: x param, LAYER==2: g_out1 with ReLU)
//   W: [K, BN] row-major (slice r of the full weight)
//   C: g_h  [N_, BN]
// BM=128, BK=16, 256 threads, TM=8, TN = BN/16
// ---------------------------------------------------------------------------
template <int K, int BN, int TN, int LAYER>
__global__ __launch_bounds__(256) void gemm_scaled_kernel(const float* __restrict__ Ax,
                                                          const float* __restrict__ Wall,
                                                          int r) {
    constexpr int BM = 128;
    constexpr int BK = 16;
    constexpr int TM = 8;
    constexpr bool RELU = (LAYER == 2);

    const float* __restrict__ A = (LAYER == 1) ? Ax : g_out1;
    const float* __restrict__ W = Wall + (size_t)r * K * BN;

    __shared__ float As[BK][BM];
    __shared__ float Bs[BK][BN];

    int tid = threadIdx.x;
    int block_m = blockIdx.x * BM;
    int tr = tid / 16;  // row group 0..15
    int tc = tid % 16;  // col group 0..15

    float acc[TM][TN];
#pragma unroll
    for (int i = 0; i < TM; i++)
#pragma unroll
        for (int j = 0; j < TN; j++) acc[i][j] = 0.0f;

    for (int kt = 0; kt < K / BK; kt++) {
        // Load A tile: 128x16 = 512 float4, 2 per thread
#pragma unroll
        for (int l = 0; l < 2; l++) {
            int idx = tid + l * 256;
            int row = idx >> 2;
            int kc = (idx & 3) * 4;
            int gr = block_m + row;
            float4 v = make_float4(0.f, 0.f, 0.f, 0.f);
            if (gr < N_) {
                v = *(const float4*)(A + (size_t)gr * K + kt * BK + kc);
                if (RELU) {
                    v.x = fmaxf(v.x, 0.f); v.y = fmaxf(v.y, 0.f);
                    v.z = fmaxf(v.z, 0.f); v.w = fmaxf(v.w, 0.f);
                }
            }
            As[kc + 0][row] = v.x;
            As[kc + 1][row] = v.y;
            As[kc + 2][row] = v.z;
            As[kc + 3][row] = v.w;
        }
        // Load B tile: BK x BN
#pragma unroll
        for (int i = tid * 4; i < BK * BN; i += 256 * 4) {
            int k = i / BN;
            int c = i % BN;
            *(float4*)&Bs[k][c] = *(const float4*)(W + (size_t)(kt * BK + k) * BN + c);
        }
        __syncthreads();

#pragma unroll
        for (int kk = 0; kk < BK; kk++) {
            float ra[TM], rb[TN];
#pragma unroll
            for (int i = 0; i < TM; i++) ra[i] = As[kk][tr * TM + i];
#pragma unroll
            for (int j = 0; j < TN; j += 4) {
                float4 b4 = *(const float4*)&Bs[kk][tc * TN + j];
                rb[j + 0] = b4.x; rb[j + 1] = b4.y; rb[j + 2] = b4.z; rb[j + 3] = b4.w;
            }
#pragma unroll
            for (int i = 0; i < TM; i++)
#pragma unroll
                for (int j = 0; j < TN; j++) acc[i][j] += ra[i] * rb[j];
        }
        __syncthreads();
    }

    // Epilogue: scale rows by rsqrt(deg_out) (commutes with the GEMM), store
#pragma unroll
    for (int i = 0; i < TM; i++) {
        int gr = block_m + tr * TM + i;
        if (gr < N_) {
            float s = g_degO[r * N_ + gr];
#pragma unroll
            for (int j = 0; j < TN; j += 4) {
                float4 v = make_float4(acc[i][j] * s, acc[i][j + 1] * s,
                                       acc[i][j + 2] * s, acc[i][j + 3] * s);
                *(float4*)(g_h + (size_t)gr * BN + tc * TN + j) = v;
            }
        }
    }
}

// ---------------------------------------------------------------------------
// Edge scatter:  out[dst] += rsqrt(deg_in[r])[dst] * h[src]
// One thread per (edge, float4-chunk). Uses vector reduction (no return).
// ---------------------------------------------------------------------------
template <int F, int LAYER>
__global__ __launch_bounds__(256) void scatter_add_kernel(const int* __restrict__ src,
                                                          const int* __restrict__ dst,
                                                          int r,
                                                          float* __restrict__ outp) {
    constexpr int P = F / 4;
    int idx = blockIdx.x * blockDim.x + threadIdx.x;
    if (idx >= E_ * P) return;
    int e = idx / P;
    int p = idx % P;
    int s = src[e];
    int d = dst[e];
    float sc = g_degI[r * N_ + d];
    float4 v = *(const float4*)(g_h + (size_t)s * F + p * 4);
    float* o = ((LAYER == 1) ? g_out1 : outp) + (size_t)d * F + p * 4;
    asm volatile("red.global.add.v4.f32 [%0], {%1, %2, %3, %4};"
                 :: "l"(o), "f"(v.x * sc), "f"(v.y * sc), "f"(v.z * sc), "f"(v.w * sc)
                 : "memory");
}

// ---------------------------------------------------------------------------
// Launch
// ---------------------------------------------------------------------------
extern "C" void kernel_launch(void* const* d_in, const int* in_sizes, int n_in,
                              void* d_out, int out_size) {
    const float* x    = (const float*)d_in[0];
    const int*   esrc = (const int*)d_in[1];
    const int*   edst = (const int*)d_in[2];
    const float* W1   = (const float*)d_in[3];
    const float* b1   = (const float*)d_in[4];
    const float* W2   = (const float*)d_in[5];
    const float* b2   = (const float*)d_in[6];
    float* out = (float*)d_out;

    // Degrees (shared by both layers)
    zero_deg_kernel<<<(R_ * N_ + 255) / 256, 256>>>();
    count_deg_kernel<<<(R_ * E_ + 255) / 256, 256>>>(esrc, edst);
    finalize_deg_kernel<<<(R_ * N_ + 255) / 256, 256>>>();

    // Layer 1
    init_out1_kernel<<<(N_ * HID_ + 255) / 256, 256>>>(b1);
    for (int r = 0; r < R_; r++) {
        gemm_scaled_kernel<IN_, HID_, 8, 1><<<(N_ + 127) / 128, 256>>>(x, W1, r);
        scatter_add_kernel<HID_, 1><<<(E_ * (HID_ / 4) + 255) / 256, 256>>>(
            esrc + r * E_, edst + r * E_, r, nullptr);
    }

    // Layer 2 (ReLU folded into GEMM A-load)
    init_out2_kernel<<<(N_ * OUT_ + 255) / 256, 256>>>(b2, out);
    for (int r = 0; r < R_; r++) {
        gemm_scaled_kernel<HID_, OUT_, 4, 2><<<(N_ + 127) / 128, 256>>>(x, W2, r);
        scatter_add_kernel<OUT_, 2><<<(E_ * (OUT_ / 4) + 255) / 256, 256>>>(
            esrc + r * E_, edst + r * E_, r, out);
    }
}

// round 5
// speedup vs baseline: 1.7308x; 1.7308x over previous
#include <cuda_runtime.h>
#include <cstdint>

// Fixed problem shapes
#define N_   100000
#define R_   4
#define E_   500000
#define IN_  256
#define HID_ 128
#define OUT_ 64

// Scratch (no allocation allowed -> device globals)
__device__ float g_h[(size_t)R_ * N_ * HID_];  // per-relation transformed features
__device__ float g_out1[(size_t)N_ * HID_];    // layer-1 accumulated output (pre-ReLU)
__device__ float g_degO[R_ * N_];              // rsqrt(max(deg_out,1))
__device__ float g_degI[R_ * N_];              // rsqrt(max(deg_in,1))

// ---------------------------------------------------------------------------
// mma.sync helpers (base-target PTX; works through compute_103 virtual arch)
// ---------------------------------------------------------------------------
__device__ __forceinline__ void mma_tf32(float* c, const uint32_t* a, const uint32_t* b) {
    asm volatile(
        "mma.sync.aligned.m16n8k8.row.col.f32.tf32.tf32.f32 "
        "{%0,%1,%2,%3}, {%4,%5,%6,%7}, {%8,%9}, {%0,%1,%2,%3};"
        : "+f"(c[0]), "+f"(c[1]), "+f"(c[2]), "+f"(c[3])
        : "r"(a[0]), "r"(a[1]), "r"(a[2]), "r"(a[3]), "r"(b[0]), "r"(b[1]));
}

__device__ __forceinline__ float to_tf32(float x) {
    float y;
    asm("cvt.rna.tf32.f32 %0, %1;" : "=f"(y) : "f"(x));
    return y;
}

__device__ __forceinline__ float4 cvt4(float4 v) {
    v.x = to_tf32(v.x); v.y = to_tf32(v.y);
    v.z = to_tf32(v.z); v.w = to_tf32(v.w);
    return v;
}

// ---------------------------------------------------------------------------
// Degree kernels
// ---------------------------------------------------------------------------
__global__ void zero_deg_kernel() {
    int i = blockIdx.x * blockDim.x + threadIdx.x;
    if (i < R_ * N_) { g_degO[i] = 0.0f; g_degI[i] = 0.0f; }
}

__global__ void count_deg_kernel(const int* __restrict__ src, const int* __restrict__ dst) {
    int i = blockIdx.x * blockDim.x + threadIdx.x;
    if (i < R_ * E_) {
        int r = i / E_;
        atomicAdd(&g_degO[r * N_ + src[i]], 1.0f);
        atomicAdd(&g_degI[r * N_ + dst[i]], 1.0f);
    }
}

__global__ void finalize_deg_kernel() {
    int i = blockIdx.x * blockDim.x + threadIdx.x;
    if (i < R_ * N_) {
        g_degO[i] = rsqrtf(fmaxf(g_degO[i], 1.0f));
        g_degI[i] = rsqrtf(fmaxf(g_degI[i], 1.0f));
    }
}

// ---------------------------------------------------------------------------
// Output init: out[n][k] = sum_r b[r][k]
// ---------------------------------------------------------------------------
__global__ void init_out1_kernel(const float* __restrict__ b1) {
    int i = blockIdx.x * blockDim.x + threadIdx.x;
    if (i < N_ * HID_) {
        int k = i & (HID_ - 1);
        float s = 0.0f;
#pragma unroll
        for (int r = 0; r < R_; r++) s += b1[r * HID_ + k];
        g_out1[i] = s;
    }
}

__global__ void init_out2_kernel(const float* __restrict__ b2, float* __restrict__ out) {
    int i = blockIdx.x * blockDim.x + threadIdx.x;
    if (i < N_ * OUT_) {
        int k = i & (OUT_ - 1);
        float s = 0.0f;
#pragma unroll
        for (int r = 0; r < R_; r++) s += b2[r * OUT_ + k];
        out[i] = s;
    }
}

// ---------------------------------------------------------------------------
// TF32 mma.sync GEMM:  C_r = diag(rsqrt_deg_out[r]) * relu?(A) * W[r]
//   A: [N_, K] fp32 row-major;  W: [R, K, BN] row-major;  C: g_h + r*N_*BN
// BM=128, BK=32, 256 threads (8 warps, 4x2 warp grid), warp tile 32 x BN/2.
// grid = (ceil(N/128), R)
// ---------------------------------------------------------------------------
template <int K, int BN, int LAYER>
__global__ __launch_bounds__(256) void gemm_mma(const float* __restrict__ Ax,
                                                const float* __restrict__ Wall) {
    constexpr int BM = 128, BK = 32;
    constexpr int WN = BN / 2;   // warp n-tile (64 / 32)
    constexpr int NT = WN / 8;   // n mma tiles per warp (8 / 4)
    constexpr int APAD = 4;      // stride 36 floats: bank = 4g+t -> conflict-free frags
    constexpr int BPAD = 8;      // stride = BN+8 (≡8 mod 32): bank = 8t+g -> conflict-free

    __shared__ float As[BM][BK + APAD];
    __shared__ float Bs[BK][BN + BPAD];

    const int tid = threadIdx.x;
    const int wid = tid >> 5, lane = tid & 31;
    const int g = lane >> 2, t = lane & 3;       // groupID, threadID-in-group
    const int wm = wid & 3, wn = wid >> 2;       // 4 x 2 warp grid
    const int r = blockIdx.y;
    const int bm = blockIdx.x * BM;

    const float* __restrict__ A = (LAYER == 1) ? Ax : g_out1;
    const float* __restrict__ W = Wall + (size_t)r * K * BN;
    float* __restrict__ C = g_h + (size_t)r * N_ * BN;

    float acc[2][NT][4];
#pragma unroll
    for (int m2 = 0; m2 < 2; m2++)
#pragma unroll
        for (int nt = 0; nt < NT; nt++)
#pragma unroll
            for (int i = 0; i < 4; i++) acc[m2][nt][i] = 0.0f;

    for (int kt = 0; kt < K / BK; kt++) {
        // A tile: 128 x 32 fp32 = 1024 float4 over 256 threads
#pragma unroll
        for (int l = 0; l < 4; l++) {
            int idx = tid + l * 256;
            int row = idx >> 3, q = idx & 7;
            int grow = bm + row;
            float4 v = make_float4(0.f, 0.f, 0.f, 0.f);
            if (grow < N_) {
                v = *(const float4*)(A + (size_t)grow * K + kt * BK + q * 4);
                if (LAYER == 2) {
                    v.x = fmaxf(v.x, 0.f); v.y = fmaxf(v.y, 0.f);
                    v.z = fmaxf(v.z, 0.f); v.w = fmaxf(v.w, 0.f);
                }
            }
            *(float4*)&As[row][q * 4] = cvt4(v);
        }
        // B tile: 32 x BN fp32 (K-major rows of W)
#pragma unroll
        for (int l = 0; l < (BK * BN / 4) / 256; l++) {
            int idx = tid + l * 256;
            int krow = idx / (BN / 4), c4 = idx % (BN / 4);
            float4 v = *(const float4*)(W + (size_t)(kt * BK + krow) * BN + c4 * 4);
            *(float4*)&Bs[krow][c4 * 4] = cvt4(v);
        }
        __syncthreads();

#pragma unroll
        for (int ks = 0; ks < BK / 8; ks++) {
            const int kb = ks * 8;
            uint32_t a[2][4];
#pragma unroll
            for (int m2 = 0; m2 < 2; m2++) {
                int row = wm * 32 + m2 * 16;
                a[m2][0] = __float_as_uint(As[row + g][kb + t]);
                a[m2][1] = __float_as_uint(As[row + 8 + g][kb + t]);
                a[m2][2] = __float_as_uint(As[row + g][kb + t + 4]);
                a[m2][3] = __float_as_uint(As[row + 8 + g][kb + t + 4]);
            }
#pragma unroll
            for (int nt = 0; nt < NT; nt++) {
                uint32_t b[2];
                int col = wn * WN + nt * 8 + g;
                b[0] = __float_as_uint(Bs[kb + t][col]);
                b[1] = __float_as_uint(Bs[kb + t + 4][col]);
                mma_tf32(acc[0][nt], a[0], b);
                mma_tf32(acc[1][nt], a[1], b);
            }
        }
        __syncthreads();
    }

    // Epilogue: scale rows by rsqrt(deg_out) (commutes with GEMM), store fp32
#pragma unroll
    for (int m2 = 0; m2 < 2; m2++) {
        int row0 = bm + wm * 32 + m2 * 16 + g;
        int row1 = row0 + 8;
        float s0 = (row0 < N_) ? g_degO[r * N_ + row0] : 0.f;
        float s1 = (row1 < N_) ? g_degO[r * N_ + row1] : 0.f;
#pragma unroll
        for (int nt = 0; nt < NT; nt++) {
            int col = wn * WN + nt * 8 + t * 2;
            if (row0 < N_) {
                float2 v = make_float2(acc[m2][nt][0] * s0, acc[m2][nt][1] * s0);
                *(float2*)(C + (size_t)row0 * BN + col) = v;
            }
            if (row1 < N_) {
                float2 v = make_float2(acc[m2][nt][2] * s1, acc[m2][nt][3] * s1);
                *(float2*)(C + (size_t)row1 * BN + col) = v;
            }
        }
    }
}

// ---------------------------------------------------------------------------
// Edge scatter (all relations, grid.y = r): out[dst] += rsqrt(deg_in)[dst]*h_r[src]
// One thread per (edge, float4-chunk); red.global.add.v4 (no return).
// ---------------------------------------------------------------------------
template <int F, int LAYER>
__global__ __launch_bounds__(256) void scatter_all_kernel(const int* __restrict__ esrc,
                                                          const int* __restrict__ edst,
                                                          float* __restrict__ outp) {
    constexpr int P = F / 4;
    const int r = blockIdx.y;
    int idx = blockIdx.x * blockDim.x + threadIdx.x;
    if (idx >= E_ * P) return;
    int e = idx / P;
    int p = idx % P;
    int s = esrc[r * E_ + e];
    int d = edst[r * E_ + e];
    float sc = g_degI[r * N_ + d];
    float4 v = *(const float4*)(g_h + (size_t)r * N_ * F + (size_t)s * F + p * 4);
    float* o = ((LAYER == 1) ? g_out1 : outp) + (size_t)d * F + p * 4;
    asm volatile("red.global.add.v4.f32 [%0], {%1, %2, %3, %4};"
                 :: "l"(o), "f"(v.x * sc), "f"(v.y * sc), "f"(v.z * sc), "f"(v.w * sc)
                 : "memory");
}

// ---------------------------------------------------------------------------
// Launch
// ---------------------------------------------------------------------------
extern "C" void kernel_launch(void* const* d_in, const int* in_sizes, int n_in,
                              void* d_out, int out_size) {
    const float* x    = (const float*)d_in[0];
    const int*   esrc = (const int*)d_in[1];
    const int*   edst = (const int*)d_in[2];
    const float* W1   = (const float*)d_in[3];
    const float* b1   = (const float*)d_in[4];
    const float* W2   = (const float*)d_in[5];
    const float* b2   = (const float*)d_in[6];
    float* out = (float*)d_out;

    const int mblocks = (N_ + 127) / 128;

    // Degrees (shared by both layers)
    zero_deg_kernel<<<(R_ * N_ + 255) / 256, 256>>>();
    count_deg_kernel<<<(R_ * E_ + 255) / 256, 256>>>(esrc, edst);
    finalize_deg_kernel<<<(R_ * N_ + 255) / 256, 256>>>();

    // Layer 1: all 4 relation GEMMs in one launch, then fused scatter
    init_out1_kernel<<<(N_ * HID_ + 255) / 256, 256>>>(b1);
    gemm_mma<IN_, HID_, 1><<<dim3(mblocks, R_), 256>>>(x, W1);
    scatter_all_kernel<HID_, 1>
        <<<dim3((E_ * (HID_ / 4) + 255) / 256, R_), 256>>>(esrc, edst, nullptr);

    // Layer 2 (ReLU folded into GEMM A-load)
    init_out2_kernel<<<(N_ * OUT_ + 255) / 256, 256>>>(b2, out);
    gemm_mma<HID_, OUT_, 2><<<dim3(mblocks, R_), 256>>>(x, W2);
    scatter_all_kernel<OUT_, 2>
        <<<dim3((E_ * (OUT_ / 4) + 255) / 256, R_), 256>>>(esrc, edst, out);
}